// round 8
// baseline (speedup 1.0000x reference)
#include <cuda_runtime.h>
#include <cuda_bf16.h>
#include <cstdint>

// ---------------- problem constants ----------------
#define NNODES 50000
#define NEDGES 800000
#define HD     256      // hidden width
#define TD2    512      // padded 4*K
#define GDC    512      // padded combine K (456 -> 512)
#define KLR    100
#define MB     391      // ceil(50000/128)

// ---------------- static scratch ----------------
__device__ float g_x[NNODES * HD];
__device__ float g_h[NNODES * HD];
__device__ float g_t[NNODES * TD2];
__device__ __nv_bfloat16 g_xhi[NNODES * HD];
__device__ __nv_bfloat16 g_xlo[NNODES * HD];
__device__ __nv_bfloat16 g_chi[NNODES * GDC];
__device__ __nv_bfloat16 g_clo[NNODES * GDC];
__device__ __nv_bfloat16 g_wh[512 * 512];
__device__ __nv_bfloat16 g_wl[512 * 512];
__device__ float g_M[KLR * KLR];
__device__ float g_cs[2 * KLR];
__device__ float g_inv_nf;
__device__ float g_mean[HD];
__device__ float g_msq[HD];
__device__ float g_scale[HD];
__device__ float g_shift[HD];
__device__ float g_dis[NNODES];
__device__ int   g_deg[NNODES];
__device__ int   g_rowptr[NNODES + 1];
__device__ int   g_cur[NNODES];
__device__ int   g_colidx[NEDGES];
__device__ int   g_bsum[64];

// ---------------- PTX helpers ----------------
__device__ __forceinline__ uint32_t smem_u32(const void* p) {
    uint32_t a;
    asm("{ .reg .u64 t; cvta.to.shared.u64 t, %1; cvt.u32.u64 %0, t; }"
        : "=r"(a) : "l"(p));
    return a;
}

__device__ __forceinline__ void cp16(uint32_t dst, const void* src, int sz) {
    asm volatile("cp.async.cg.shared.global [%0], [%1], 16, %2;"
                 :: "r"(dst), "l"(src), "r"(sz) : "memory");
}

__device__ __forceinline__ void ldm_x4(uint32_t* r, uint32_t addr) {
    asm volatile("ldmatrix.sync.aligned.m8n8.x4.shared.b16 {%0,%1,%2,%3}, [%4];"
                 : "=r"(r[0]), "=r"(r[1]), "=r"(r[2]), "=r"(r[3]) : "r"(addr));
}

__device__ __forceinline__ void mma_bf16(float* d, const uint32_t* a,
                                         const uint32_t* b) {
    asm volatile(
        "mma.sync.aligned.m16n8k16.row.col.f32.bf16.bf16.f32 "
        "{%0,%1,%2,%3}, {%4,%5,%6,%7}, {%8,%9}, {%0,%1,%2,%3};"
        : "+f"(d[0]), "+f"(d[1]), "+f"(d[2]), "+f"(d[3])
        : "r"(a[0]), "r"(a[1]), "r"(a[2]), "r"(a[3]), "r"(b[0]), "r"(b[1]));
}

// ---------------- HMMA GEMM: C = act(A@B^T + bias) ----------------
// CTA tile 128 x 64, BK=64, 8 warps 4(M)x2(N), warp tile 32x32.
// 2-stage cp.async pipeline, 2 CTAs/SM, register fragment double-buffering.
// kk-advance on swizzled addresses is XOR(kk*32): base bits 5-6 are zero and
// the XOR source bits (7-9) are unchanged, so sw(off+kk*32) == sw(off)^(kk*32).
#define STAGE_BYTES 49152
__global__ void __launch_bounds__(256, 2)
mma_gemm(const __nv_bfloat16* __restrict__ Ah, const __nv_bfloat16* __restrict__ Al,
         const __nv_bfloat16* __restrict__ Bh, const __nv_bfloat16* __restrict__ Bl,
         const float* __restrict__ bias, float* __restrict__ C,
         int M, int K, int ldc, int nvalid, int relu) {
    extern __shared__ char dsm_raw[];
    uint32_t base0 = (smem_u32(dsm_raw) + 1023u) & ~1023u;
    const int tid = threadIdx.x;
    const int wid = tid >> 5;
    const int lane = tid & 31;
    const int wm = wid & 3;       // 0..3 -> 32-row group
    const int wn = wid >> 2;      // 0..1 -> 32-col group
    const int row0 = blockIdx.y * 128;
    const int col0 = blockIdx.x * 64;
    const __nv_bfloat16* Bh0 = Bh + (size_t)col0 * K;
    const __nv_bfloat16* Bl0 = Bl + (size_t)col0 * K;
    const int nc = K >> 6;

    float acc[2][4][4];
#pragma unroll
    for (int mt = 0; mt < 2; mt++)
#pragma unroll
        for (int nt = 0; nt < 4; nt++)
#pragma unroll
            for (int q = 0; q < 4; q++) acc[mt][nt][q] = 0.f;

    auto load_chunk = [&](int c) {
        uint32_t sb = base0 + (uint32_t)(c & 1) * STAGE_BYTES;
        int k0 = c << 6;
#pragma unroll 4
        for (int j = 0; j < 4; j++) {
            int i = tid + j * 256;
            int r = i >> 3, seg = i & 7;
            int off = r * 128 + seg * 16;
            uint32_t sw = (uint32_t)(off ^ ((off >> 3) & 0x70));
            int ga = row0 + r;
            int ok = (ga < M) ? 16 : 0;
            if (ga >= M) ga = 0;
            size_t ao = (size_t)ga * K + k0 + seg * 8;
            cp16(sb + sw,         Ah + ao, ok);
            cp16(sb + 16384 + sw, Al + ao, ok);
        }
        {
            int i = tid;
            int r = i >> 3, seg = i & 7;
            int off = r * 128 + seg * 16;
            uint32_t sw = (uint32_t)(off ^ ((off >> 3) & 0x70));
            size_t bo = (size_t)r * K + k0 + seg * 8;
            cp16(sb + 32768 + sw, Bh0 + bo, 16);
            cp16(sb + 40960 + sw, Bl0 + bo, 16);
        }
        {
            int i = tid + 256;
            int r = i >> 3, seg = i & 7;
            int off = r * 128 + seg * 16;
            uint32_t sw = (uint32_t)(off ^ ((off >> 3) & 0x70));
            size_t bo = (size_t)r * K + k0 + seg * 8;
            cp16(sb + 32768 + sw, Bh0 + bo, 16);
            cp16(sb + 40960 + sw, Bl0 + bo, 16);
        }
        asm volatile("cp.async.commit_group;" ::: "memory");
    };

    // fragment base smem offsets (bits 5-6 of the unswizzled base are zero)
    const int a_off0 = (wm * 32 + (lane & 15)) * 128 + ((lane >> 4) << 4);
    const int b_off0 = (wn * 32 + ((lane >> 4) << 3) + (lane & 7)) * 128
                     + (((lane >> 3) & 1) << 4);
    const uint32_t a_sw0 = (uint32_t)(a_off0 ^ ((a_off0 >> 3) & 0x70));
    const uint32_t b_sw0 = (uint32_t)(b_off0 ^ ((b_off0 >> 3) & 0x70));

    uint32_t ah[2][2][4], al[2][2][4], bh[2][2][4], bl[2][2][4];

    auto ld_frags = [&](uint32_t sb, int kk, int buf) {
        const uint32_t kx = (uint32_t)(kk * 32);
#pragma unroll
        for (int mt = 0; mt < 2; mt++) {
            uint32_t ad = (sb + a_sw0 + mt * 2048) ^ kx;
            ldm_x4(ah[buf][mt], ad);
            ldm_x4(al[buf][mt], ad + 16384);
        }
#pragma unroll
        for (int np = 0; np < 2; np++) {
            uint32_t ad = (sb + b_sw0 + np * 2048) ^ kx;
            ldm_x4(bh[buf][np], ad + 32768);
            ldm_x4(bl[buf][np], ad + 40960);
        }
    };

    load_chunk(0);
    for (int c = 0; c < nc; c++) {
        if (c + 1 < nc) {
            load_chunk(c + 1);
            asm volatile("cp.async.wait_group 1;" ::: "memory");
        } else {
            asm volatile("cp.async.wait_group 0;" ::: "memory");
        }
        __syncthreads();
        uint32_t sb = base0 + (uint32_t)(c & 1) * STAGE_BYTES;
        ld_frags(sb, 0, 0);
#pragma unroll
        for (int kk = 0; kk < 4; kk++) {
            int cur = kk & 1, nxt = cur ^ 1;
            if (kk < 3) ld_frags(sb, kk + 1, nxt);   // overlap LDSM with HMMA
#pragma unroll
            for (int mt = 0; mt < 2; mt++)
#pragma unroll
                for (int nt = 0; nt < 4; nt++) {
                    const uint32_t* bhp = &bh[cur][nt >> 1][(nt & 1) * 2];
                    const uint32_t* blp = &bl[cur][nt >> 1][(nt & 1) * 2];
                    mma_bf16(acc[mt][nt], ah[cur][mt], bhp);
                    mma_bf16(acc[mt][nt], ah[cur][mt], blp);
                    mma_bf16(acc[mt][nt], al[cur][mt], bhp);
                }
        }
        __syncthreads();
    }

    // epilogue
#pragma unroll
    for (int mt = 0; mt < 2; mt++) {
        int ra = row0 + wm * 32 + mt * 16 + (lane >> 2);
        int rb = ra + 8;
#pragma unroll
        for (int nt = 0; nt < 4; nt++) {
            int c0 = col0 + wn * 32 + nt * 8 + (lane & 3) * 2;
            float bv0 = 0.f, bv1 = 0.f;
            if (bias && c0 < nvalid) {
                bv0 = __ldg(&bias[c0]);
                bv1 = __ldg(&bias[c0 + 1]);
            }
            float v0 = acc[mt][nt][0] + bv0;
            float v1 = acc[mt][nt][1] + bv1;
            float v2 = acc[mt][nt][2] + bv0;
            float v3 = acc[mt][nt][3] + bv1;
            if (relu) {
                v0 = fmaxf(v0, 0.f); v1 = fmaxf(v1, 0.f);
                v2 = fmaxf(v2, 0.f); v3 = fmaxf(v3, 0.f);
            }
            if (ra < M) *(float2*)&C[(size_t)ra * ldc + c0] = make_float2(v0, v1);
            if (rb < M) *(float2*)&C[(size_t)rb * ldc + c0] = make_float2(v2, v3);
        }
    }
}

// ---------------- conversion kernels ----------------
__global__ void xsplit_kernel(const float* __restrict__ x, long n) {
    long i = (long)blockIdx.x * blockDim.x + threadIdx.x;
    if (i < n) {
        float v = x[i];
        __nv_bfloat16 hi = __float2bfloat16(v);
        g_xhi[i] = hi;
        g_xlo[i] = __float2bfloat16(v - __bfloat162float(hi));
    }
}

__global__ void wsplit_kernel(const float* __restrict__ W, int K, int N,
                              int Nout, int Kpad) {
    int i = blockIdx.x * blockDim.x + threadIdx.x;
    if (i < Nout * Kpad) {
        int n = i / Kpad, k = i - n * Kpad;
        float v = (n < N && k < K) ? W[(size_t)k * N + n] : 0.f;
        __nv_bfloat16 hi = __float2bfloat16(v);
        g_wh[i] = hi;
        g_wl[i] = __float2bfloat16(v - __bfloat162float(hi));
    }
}

__global__ void padzero_kernel() {
    int v = blockIdx.x, c = threadIdx.x;
    if (c < GDC - 456) {
        size_t o = (size_t)v * GDC + 456 + c;
        g_chi[o] = __float2bfloat16(0.f);
        g_clo[o] = __float2bfloat16(0.f);
    }
}

// ---------------- graph setup ----------------
__global__ void zero_deg_kernel() {
    int i = blockIdx.x * blockDim.x + threadIdx.x;
    if (i < NNODES) g_deg[i] = 0;
}

__global__ void count_deg_kernel(const int* __restrict__ dst) {
    for (int e = blockIdx.x * blockDim.x + threadIdx.x; e < NEDGES;
         e += gridDim.x * blockDim.x)
        atomicAdd(&g_deg[dst[e]], 1);
}

__global__ void scan1_kernel() {
    __shared__ int s[1024];
    int tid = threadIdx.x;
    int i = blockIdx.x * 1024 + tid;
    int v = (i < NNODES) ? g_deg[i] : 0;
    s[tid] = v;
    __syncthreads();
    for (int off = 1; off < 1024; off <<= 1) {
        int t = (tid >= off) ? s[tid - off] : 0;
        __syncthreads();
        s[tid] += t;
        __syncthreads();
    }
    if (i < NNODES) g_rowptr[i + 1] = s[tid];
    if (tid == 1023) g_bsum[blockIdx.x] = s[1023];
}

__global__ void scan2_kernel() {
    int acc = 0;
    for (int b = 0; b < 49; b++) { int t = g_bsum[b]; g_bsum[b] = acc; acc += t; }
}

__global__ void scan3_kernel() {
    int i = blockIdx.x * 1024 + threadIdx.x;
    if (i == 0) g_rowptr[0] = 0;
    if (i < NNODES) {
        int incl = g_rowptr[i + 1] + g_bsum[blockIdx.x];
        g_rowptr[i + 1] = incl;
        g_cur[i] = incl - g_deg[i];
        g_dis[i] = rsqrtf((float)(g_deg[i] + 1));
    }
}

__global__ void fill_csr_kernel(const int* __restrict__ src,
                                const int* __restrict__ dst) {
    for (int e = blockIdx.x * blockDim.x + threadIdx.x; e < NEDGES;
         e += gridDim.x * blockDim.x) {
        int d = dst[e];
        int p = atomicAdd(&g_cur[d], 1);
        g_colidx[p] = src[e];
    }
}

// ---------------- low-rank path ----------------
__global__ void zero_misc_kernel() {
    int i = blockIdx.x * blockDim.x + threadIdx.x;
    if (i < KLR * KLR) g_M[i] = 0.f;
    if (i < 2 * KLR)   g_cs[i] = 0.f;
    if (i < HD)        { g_mean[i] = 0.f; g_msq[i] = 0.f; }
}

__global__ void colsum_kernel() {
    int col = threadIdx.x;
    int r0 = blockIdx.x * 256;
    if (col < 2 * KLR) {
        float s = 0.f;
        int rend = min(r0 + 256, NNODES);
        for (int r = r0; r < rend; r++) s += g_t[(size_t)r * TD2 + col];
        atomicAdd(&g_cs[col], s);
    }
}

__global__ void nf_kernel() {
    int lane = threadIdx.x;
    float s = 0.f;
    for (int k = lane; k < KLR; k += 32) s += g_cs[k] * g_cs[KLR + k];
#pragma unroll
    for (int o = 16; o > 0; o >>= 1) s += __shfl_down_sync(0xffffffffu, s, o);
    if (lane == 0) g_inv_nf = 1.0f / (s / (float)NNODES + 1e-6f);
}

// M = V^T @ Z (100x100): 200 k-split blocks, 7x7 register tile per thread.
__global__ void __launch_bounds__(256) vtz_kernel() {
    __shared__ float Vs[32][112];
    __shared__ float Zs[32][112];
    const int tid = threadIdx.x;
    const int i = tid >> 4;
    const int j = tid & 15;
    const int kbeg = blockIdx.x * 250;
    const int kend = min(kbeg + 250, NNODES);

    float acc[7][7];
#pragma unroll
    for (int p = 0; p < 7; p++)
#pragma unroll
        for (int q = 0; q < 7; q++) acc[p][q] = 0.f;

    for (int k0 = kbeg; k0 < kend; k0 += 32) {
        int km = kend - k0;
        for (int idx = tid; idx < 32 * 112; idx += 256) {
            int kk = idx / 112, cc = idx - kk * 112;
            float v = 0.f, z = 0.f;
            if (kk < km && cc < KLR) {
                size_t b = (size_t)(k0 + kk) * TD2;
                v = g_t[b + KLR + cc];
                z = g_t[b + 2 * KLR + cc];
            }
            Vs[kk][cc] = v;
            Zs[kk][cc] = z;
        }
        __syncthreads();
#pragma unroll 4
        for (int kk = 0; kk < 32; kk++) {
            float av[7], bz[7];
#pragma unroll
            for (int p = 0; p < 7; p++) av[p] = Vs[kk][i + 16 * p];
#pragma unroll
            for (int q = 0; q < 7; q++) bz[q] = Zs[kk][j + 16 * q];
#pragma unroll
            for (int p = 0; p < 7; p++)
#pragma unroll
                for (int q = 0; q < 7; q++)
                    acc[p][q] = fmaf(av[p], bz[q], acc[p][q]);
        }
        __syncthreads();
    }
#pragma unroll
    for (int p = 0; p < 7; p++) {
        int r = i + 16 * p;
        if (r >= KLR) break;
#pragma unroll
        for (int q = 0; q < 7; q++) {
            int c = j + 16 * q;
            if (c < KLR) atomicAdd(&g_M[r * KLR + c], acc[p][q]);
        }
    }
}

// packed combine cols 0..199 = [res/nf | T] as bf16 hi/lo
__global__ void __launch_bounds__(256) respack_kernel() {
    __shared__ float Msh[KLR * KLR];
    __shared__ float Ush[16 * KLR];
    int tid = threadIdx.x;
    int r0 = blockIdx.x * 16;
    for (int idx = tid; idx < KLR * KLR; idx += 256) Msh[idx] = g_M[idx];
    for (int idx = tid; idx < 16 * KLR; idx += 256) {
        int r = idx / KLR, c = idx % KLR;
        Ush[idx] = (r0 + r < NNODES) ? g_t[(size_t)(r0 + r) * TD2 + c] : 0.f;
    }
    __syncthreads();
    float inv = g_inv_nf;
    int r = tid >> 4;
    int cg = tid & 15;
    if (r0 + r < NNODES) {
        float acc[7];
#pragma unroll
        for (int q = 0; q < 7; q++) acc[q] = 0.f;
        for (int k = 0; k < KLR; k++) {
            float a = Ush[r * KLR + k];
#pragma unroll
            for (int q = 0; q < 7; q++) {
                int c = cg + q * 16;
                if (c < KLR) acc[q] = fmaf(a, Msh[k * KLR + c], acc[q]);
            }
        }
        size_t base = (size_t)(r0 + r) * GDC;
#pragma unroll
        for (int q = 0; q < 7; q++) {
            int c = cg + q * 16;
            if (c < KLR) {
                float v = acc[q] * inv;
                __nv_bfloat16 hi = __float2bfloat16(v);
                g_chi[base + c] = hi;
                g_clo[base + c] = __float2bfloat16(v - __bfloat162float(hi));
            }
        }
#pragma unroll
        for (int q = 0; q < 7; q++) {
            int c = cg + q * 16;
            if (c < KLR) {
                float v = g_t[(size_t)(r0 + r) * TD2 + 3 * KLR + c];
                __nv_bfloat16 hi = __float2bfloat16(v);
                g_chi[base + KLR + c] = hi;
                g_clo[base + KLR + c] = __float2bfloat16(v - __bfloat162float(hi));
            }
        }
    }
}

// cols 200..455 of combine input = relu(aggregate + cb) as bf16 hi/lo
__global__ void agg_kernel(const float* __restrict__ cb) {
    __shared__ int   sh_u[64];
    __shared__ float sh_w[64];
    const int v = blockIdx.x;
    const int c = threadIdx.x;
    const float dv = g_dis[v];
    float acc = g_h[(size_t)v * HD + c] * dv * dv;
    const int s0 = g_rowptr[v], e0 = g_rowptr[v + 1];
    for (int s = s0; s < e0; s += 64) {
        int m = min(64, e0 - s);
        __syncthreads();
        if (c < m) {
            int u = g_colidx[s + c];
            sh_u[c] = u;
            sh_w[c] = g_dis[u] * dv;
        }
        __syncthreads();
        int j = 0;
        for (; j + 4 <= m; j += 4) {
            float h0 = g_h[(size_t)sh_u[j + 0] * HD + c];
            float h1 = g_h[(size_t)sh_u[j + 1] * HD + c];
            float h2 = g_h[(size_t)sh_u[j + 2] * HD + c];
            float h3 = g_h[(size_t)sh_u[j + 3] * HD + c];
            acc = fmaf(h0, sh_w[j + 0], acc);
            acc = fmaf(h1, sh_w[j + 1], acc);
            acc = fmaf(h2, sh_w[j + 2], acc);
            acc = fmaf(h3, sh_w[j + 3], acc);
        }
        for (; j < m; j++)
            acc = fmaf(g_h[(size_t)sh_u[j] * HD + c], sh_w[j], acc);
    }
    acc = fmaxf(acc + cb[c], 0.f);
    __nv_bfloat16 hi = __float2bfloat16(acc);
    size_t o = (size_t)v * GDC + 200 + c;
    g_chi[o] = hi;
    g_clo[o] = __float2bfloat16(acc - __bfloat162float(hi));
}

// ---------------- batch norm ----------------
__global__ void bn_stats_kernel() {
    int col = threadIdx.x;
    int r0 = blockIdx.x * 128;
    int rend = min(r0 + 128, NNODES);
    float s = 0.f, s2 = 0.f;
    for (int r = r0; r < rend; r++) {
        float v = g_x[(size_t)r * HD + col];
        s += v;
        s2 = fmaf(v, v, s2);
    }
    atomicAdd(&g_mean[col], s);
    atomicAdd(&g_msq[col], s2);
}

__global__ void bn_final_kernel(const float* __restrict__ gam,
                                const float* __restrict__ bet) {
    int c = threadIdx.x;
    float m = g_mean[c] / (float)NNODES;
    float var = g_msq[c] / (float)NNODES - m * m;
    float sc = gam[c] * rsqrtf(var + 1e-5f);
    g_scale[c] = sc;
    g_shift[c] = bet[c] - m * sc;
}

__global__ void bn_apply_kernel() {
    size_t i = (size_t)blockIdx.x * blockDim.x + threadIdx.x;
    if (i < (size_t)NNODES * HD) {
        int c = (int)(i & (HD - 1));
        float v = fmaf(g_x[i], g_scale[c], g_shift[c]);
        g_x[i] = v;
        __nv_bfloat16 hi = __float2bfloat16(v);
        g_xhi[i] = hi;
        g_xlo[i] = __float2bfloat16(v - __bfloat162float(hi));
    }
}

// ---------------- host orchestration ----------------
extern "C" void kernel_launch(void* const* d_in, const int* in_sizes, int n_in,
                              void* d_out, int out_size) {
    (void)in_sizes; (void)n_in; (void)out_size;
    const float* x_in = (const float*)d_in[0];
    const int*   ei   = (const int*)d_in[1];
    const int*   src  = ei;
    const int*   dst  = ei + NEDGES;

    const float* cw[3] = {(const float*)d_in[2],  (const float*)d_in[8],  (const float*)d_in[14]};
    const float* cb[3] = {(const float*)d_in[3],  (const float*)d_in[9],  (const float*)d_in[15]};
    const float* aw[3] = {(const float*)d_in[4],  (const float*)d_in[10], (const float*)d_in[16]};
    const float* ab[3] = {(const float*)d_in[5],  (const float*)d_in[11], (const float*)d_in[17]};
    const float* rw[3] = {(const float*)d_in[6],  (const float*)d_in[12], (const float*)d_in[18]};
    const float* rb[3] = {(const float*)d_in[7],  (const float*)d_in[13], (const float*)d_in[19]};
    const float* gam[2] = {(const float*)d_in[20], (const float*)d_in[22]};
    const float* bet[2] = {(const float*)d_in[21], (const float*)d_in[23]};
    float* out = (float*)d_out;

    float *p_x, *p_h, *p_t;
    __nv_bfloat16 *p_xhi, *p_xlo, *p_chi, *p_clo, *p_wh, *p_wl;
    cudaGetSymbolAddress((void**)&p_x, g_x);
    cudaGetSymbolAddress((void**)&p_h, g_h);
    cudaGetSymbolAddress((void**)&p_t, g_t);
    cudaGetSymbolAddress((void**)&p_xhi, g_xhi);
    cudaGetSymbolAddress((void**)&p_xlo, g_xlo);
    cudaGetSymbolAddress((void**)&p_chi, g_chi);
    cudaGetSymbolAddress((void**)&p_clo, g_clo);
    cudaGetSymbolAddress((void**)&p_wh, g_wh);
    cudaGetSymbolAddress((void**)&p_wl, g_wl);

    const int SMB = 2 * STAGE_BYTES + 1024;

    static cudaStream_t s2 = nullptr;
    static cudaEvent_t evFork = nullptr, evH = nullptr, evAgg = nullptr;
    if (s2 == nullptr) {
        cudaFuncSetAttribute(mma_gemm, cudaFuncAttributeMaxDynamicSharedMemorySize, SMB);
        cudaStreamCreateWithFlags(&s2, cudaStreamNonBlocking);
        cudaEventCreateWithFlags(&evFork, cudaEventDisableTiming);
        cudaEventCreateWithFlags(&evH, cudaEventDisableTiming);
        cudaEventCreateWithFlags(&evAgg, cudaEventDisableTiming);
    }

    // ---- fork side stream: CSR setup + pad zero (independent of GEMMs) ----
    cudaEventRecord(evFork, 0);
    cudaStreamWaitEvent(s2, evFork, 0);
    padzero_kernel<<<NNODES, 64, 0, s2>>>();
    zero_deg_kernel<<<(NNODES + 255) / 256, 256, 0, s2>>>();
    count_deg_kernel<<<800, 256, 0, s2>>>(dst);
    scan1_kernel<<<49, 1024, 0, s2>>>();
    scan2_kernel<<<1, 1, 0, s2>>>();
    scan3_kernel<<<49, 1024, 0, s2>>>();
    fill_csr_kernel<<<800, 256, 0, s2>>>(src, dst);

    // ---- main stream: input conversion ----
    xsplit_kernel<<<(NNODES * 128 + 255) / 256, 256>>>(x_in, (long)NNODES * 128);

    int din = 128;
    for (int l = 0; l < 3; l++) {
        // h = x @ cw  (main stream)
        wsplit_kernel<<<(HD * din + 255) / 256, 256>>>(cw[l], din, HD, HD, din);
        mma_gemm<<<dim3(HD / 64, MB), 256, SMB>>>(
            p_xhi, p_xlo, p_wh, p_wl, nullptr, p_h, NNODES, din, HD, HD, 0);
        cudaEventRecord(evH, 0);

        // side stream: aggregation (overlaps t GEMM + low-rank on main)
        cudaStreamWaitEvent(s2, evH, 0);
        agg_kernel<<<NNODES, HD, 0, s2>>>(cb[l]);
        cudaEventRecord(evAgg, s2);

        // main stream: t = relu(x @ aw + ab) + low-rank path
        wsplit_kernel<<<(512 * din + 255) / 256, 256>>>(aw[l], din, 400, 512, din);
        mma_gemm<<<dim3(8, MB), 256, SMB>>>(
            p_xhi, p_xlo, p_wh, p_wl, ab[l], p_t, NNODES, din, TD2, 400, 1);
        zero_misc_kernel<<<(KLR * KLR + 255) / 256, 256>>>();
        colsum_kernel<<<(NNODES + 255) / 256, 256>>>();
        nf_kernel<<<1, 32>>>();
        vtz_kernel<<<200, 256>>>();
        respack_kernel<<<NNODES / 16, 256>>>();

        // join: combine needs agg output
        cudaStreamWaitEvent(0, evAgg, 0);
        int dout = (l < 2) ? HD : 128;
        wsplit_kernel<<<(dout * 512 + 255) / 256, 256>>>(rw[l], 456, dout, dout, 512);
        if (l < 2) {
            mma_gemm<<<dim3(dout / 64, MB), 256, SMB>>>(
                p_chi, p_clo, p_wh, p_wl, rb[l], p_x, NNODES, GDC, HD, dout, 1);
            bn_stats_kernel<<<(NNODES + 127) / 128, 256>>>();
            bn_final_kernel<<<1, HD>>>(gam[l], bet[l]);
            bn_apply_kernel<<<(NNODES * HD + 255) / 256, 256>>>();
            din = HD;
        } else {
            mma_gemm<<<dim3(2, MB), 256, SMB>>>(
                p_chi, p_clo, p_wh, p_wl, rb[l], out, NNODES, GDC, 128, 128, 0);
        }
    }
}

// round 9
// speedup vs baseline: 1.0159x; 1.0159x over previous
#include <cuda_runtime.h>
#include <cuda_bf16.h>
#include <cstdint>

// ---------------- problem constants ----------------
#define NNODES 50000
#define NEDGES 800000
#define HD     256      // hidden width
#define TD2    512      // padded 4*K (row stride of g_t)
#define GDC    512      // padded combine K (456 -> 512)
#define KLR    100
#define MB     391      // ceil(50000/128)
#define WSLOT  (512 * 512)

// ---------------- static scratch ----------------
__device__ float g_x[NNODES * HD];
__device__ float g_h[NNODES * HD];
__device__ float g_t[NNODES * TD2];
__device__ __nv_bfloat16 g_xhi[NNODES * HD];
__device__ __nv_bfloat16 g_xlo[NNODES * HD];
__device__ __nv_bfloat16 g_chi[NNODES * GDC];
__device__ __nv_bfloat16 g_clo[NNODES * GDC];
__device__ __nv_bfloat16 g_wh[9 * WSLOT];   // 9 pre-split weights (hi)
__device__ __nv_bfloat16 g_wl[9 * WSLOT];   // 9 pre-split weights (lo)
__device__ float g_M[KLR * KLR];
__device__ float g_cs[2 * KLR];
__device__ float g_inv_nf;
__device__ float g_mean[HD];
__device__ float g_msq[HD];
__device__ float g_scale[HD];
__device__ float g_shift[HD];
__device__ float g_dis[NNODES];
__device__ int   g_deg[NNODES];
__device__ int   g_rowptr[NNODES + 1];
__device__ int   g_cur[NNODES];
__device__ int   g_colidx[NEDGES];
__device__ int   g_bsum[64];

// ---------------- PTX helpers ----------------
__device__ __forceinline__ uint32_t smem_u32(const void* p) {
    uint32_t a;
    asm("{ .reg .u64 t; cvta.to.shared.u64 t, %1; cvt.u32.u64 %0, t; }"
        : "=r"(a) : "l"(p));
    return a;
}

__device__ __forceinline__ void cp16(uint32_t dst, const void* src, int sz) {
    asm volatile("cp.async.cg.shared.global [%0], [%1], 16, %2;"
                 :: "r"(dst), "l"(src), "r"(sz) : "memory");
}

__device__ __forceinline__ void ldm_x4(uint32_t* r, uint32_t addr) {
    asm volatile("ldmatrix.sync.aligned.m8n8.x4.shared.b16 {%0,%1,%2,%3}, [%4];"
                 : "=r"(r[0]), "=r"(r[1]), "=r"(r[2]), "=r"(r[3]) : "r"(addr));
}

__device__ __forceinline__ void mma_bf16(float* d, const uint32_t* a,
                                         const uint32_t* b) {
    asm volatile(
        "mma.sync.aligned.m16n8k16.row.col.f32.bf16.bf16.f32 "
        "{%0,%1,%2,%3}, {%4,%5,%6,%7}, {%8,%9}, {%0,%1,%2,%3};"
        : "+f"(d[0]), "+f"(d[1]), "+f"(d[2]), "+f"(d[3])
        : "r"(a[0]), "r"(a[1]), "r"(a[2]), "r"(a[3]), "r"(b[0]), "r"(b[1]));
}

// ---------------- HMMA GEMM (round-6 proven config) ----------------
// CTA tile 128 x 64, BK=64, 8 warps 4(M)x2(N), warp tile 32x32.
// 2-stage cp.async pipeline, 2 CTAs/SM. B fragments via ldmatrix.x4.
#define STAGE_BYTES 49152
__global__ void __launch_bounds__(256, 2)
mma_gemm(const __nv_bfloat16* __restrict__ Ah, const __nv_bfloat16* __restrict__ Al,
         const __nv_bfloat16* __restrict__ Bh, const __nv_bfloat16* __restrict__ Bl,
         const float* __restrict__ bias, float* __restrict__ C,
         int M, int K, int ldc, int nvalid, int relu) {
    extern __shared__ char dsm_raw[];
    uint32_t base0 = (smem_u32(dsm_raw) + 1023u) & ~1023u;
    const int tid = threadIdx.x;
    const int wid = tid >> 5;
    const int lane = tid & 31;
    const int wm = wid & 3;
    const int wn = wid >> 2;
    const int row0 = blockIdx.y * 128;
    const int col0 = blockIdx.x * 64;
    const __nv_bfloat16* Bh0 = Bh + (size_t)col0 * K;
    const __nv_bfloat16* Bl0 = Bl + (size_t)col0 * K;
    const int nc = K >> 6;

    float acc[2][4][4];
#pragma unroll
    for (int mt = 0; mt < 2; mt++)
#pragma unroll
        for (int nt = 0; nt < 4; nt++)
#pragma unroll
            for (int q = 0; q < 4; q++) acc[mt][nt][q] = 0.f;

    auto load_chunk = [&](int c) {
        uint32_t sb = base0 + (uint32_t)(c & 1) * STAGE_BYTES;
        int k0 = c << 6;
#pragma unroll 4
        for (int j = 0; j < 4; j++) {
            int i = tid + j * 256;
            int r = i >> 3, seg = i & 7;
            int off = r * 128 + seg * 16;
            uint32_t sw = (uint32_t)(off ^ ((off >> 3) & 0x70));
            int ga = row0 + r;
            int ok = (ga < M) ? 16 : 0;
            if (ga >= M) ga = 0;
            size_t ao = (size_t)ga * K + k0 + seg * 8;
            cp16(sb + sw,         Ah + ao, ok);
            cp16(sb + 16384 + sw, Al + ao, ok);
        }
        {
            int i = tid;
            int r = i >> 3, seg = i & 7;
            int off = r * 128 + seg * 16;
            uint32_t sw = (uint32_t)(off ^ ((off >> 3) & 0x70));
            size_t bo = (size_t)r * K + k0 + seg * 8;
            cp16(sb + 32768 + sw, Bh0 + bo, 16);
            cp16(sb + 40960 + sw, Bl0 + bo, 16);
        }
        {
            int i = tid + 256;
            int r = i >> 3, seg = i & 7;
            int off = r * 128 + seg * 16;
            uint32_t sw = (uint32_t)(off ^ ((off >> 3) & 0x70));
            size_t bo = (size_t)r * K + k0 + seg * 8;
            cp16(sb + 32768 + sw, Bh0 + bo, 16);
            cp16(sb + 40960 + sw, Bl0 + bo, 16);
        }
        asm volatile("cp.async.commit_group;" ::: "memory");
    };

    const int a_off0 = (wm * 32 + (lane & 15)) * 128 + ((lane >> 4) << 4);
    const int b_off0 = (wn * 32 + ((lane >> 4) << 3) + (lane & 7)) * 128
                     + (((lane >> 3) & 1) << 4);

    load_chunk(0);
    for (int c = 0; c < nc; c++) {
        if (c + 1 < nc) {
            load_chunk(c + 1);
            asm volatile("cp.async.wait_group 1;" ::: "memory");
        } else {
            asm volatile("cp.async.wait_group 0;" ::: "memory");
        }
        __syncthreads();
        uint32_t sb = base0 + (uint32_t)(c & 1) * STAGE_BYTES;
#pragma unroll
        for (int kk = 0; kk < 4; kk++) {
            uint32_t ah[2][4], al[2][4], bh[2][4], bl[2][4];
#pragma unroll
            for (int mt = 0; mt < 2; mt++) {
                int off = a_off0 + mt * 2048 + kk * 32;
                uint32_t sw = (uint32_t)(off ^ ((off >> 3) & 0x70));
                ldm_x4(ah[mt], sb + sw);
                ldm_x4(al[mt], sb + 16384 + sw);
            }
#pragma unroll
            for (int np = 0; np < 2; np++) {
                int off = b_off0 + np * 2048 + kk * 32;
                uint32_t sw = (uint32_t)(off ^ ((off >> 3) & 0x70));
                ldm_x4(bh[np], sb + 32768 + sw);
                ldm_x4(bl[np], sb + 40960 + sw);
            }
#pragma unroll
            for (int mt = 0; mt < 2; mt++)
#pragma unroll
                for (int nt = 0; nt < 4; nt++) {
                    const uint32_t* bhp = &bh[nt >> 1][(nt & 1) * 2];
                    const uint32_t* blp = &bl[nt >> 1][(nt & 1) * 2];
                    mma_bf16(acc[mt][nt], ah[mt], bhp);
                    mma_bf16(acc[mt][nt], ah[mt], blp);
                    mma_bf16(acc[mt][nt], al[mt], bhp);
                }
        }
        __syncthreads();
    }

    // epilogue
#pragma unroll
    for (int mt = 0; mt < 2; mt++) {
        int ra = row0 + wm * 32 + mt * 16 + (lane >> 2);
        int rb = ra + 8;
#pragma unroll
        for (int nt = 0; nt < 4; nt++) {
            int c0 = col0 + wn * 32 + nt * 8 + (lane & 3) * 2;
            float bv0 = 0.f, bv1 = 0.f;
            if (bias && c0 < nvalid) {
                bv0 = __ldg(&bias[c0]);
                bv1 = __ldg(&bias[c0 + 1]);
            }
            float v0 = acc[mt][nt][0] + bv0;
            float v1 = acc[mt][nt][1] + bv1;
            float v2 = acc[mt][nt][2] + bv0;
            float v3 = acc[mt][nt][3] + bv1;
            if (relu) {
                v0 = fmaxf(v0, 0.f); v1 = fmaxf(v1, 0.f);
                v2 = fmaxf(v2, 0.f); v3 = fmaxf(v3, 0.f);
            }
            if (ra < M) *(float2*)&C[(size_t)ra * ldc + c0] = make_float2(v0, v1);
            if (rb < M) *(float2*)&C[(size_t)rb * ldc + c0] = make_float2(v2, v3);
        }
    }
}

// ---------------- conversion kernels ----------------
__global__ void xsplit_kernel(const float* __restrict__ x, long n) {
    long i = (long)blockIdx.x * blockDim.x + threadIdx.x;
    if (i < n) {
        float v = x[i];
        __nv_bfloat16 hi = __float2bfloat16(v);
        g_xhi[i] = hi;
        g_xlo[i] = __float2bfloat16(v - __bfloat162float(hi));
    }
}

// W[K x N] fp32 -> transposed padded bf16 split into slot: [Nout x Kpad]
__global__ void wsplit_kernel(const float* __restrict__ W, int K, int N,
                              int Nout, int Kpad, int slot) {
    int i = blockIdx.x * blockDim.x + threadIdx.x;
    if (i < Nout * Kpad) {
        int n = i / Kpad, k = i - n * Kpad;
        float v = (n < N && k < K) ? W[(size_t)k * N + n] : 0.f;
        __nv_bfloat16 hi = __float2bfloat16(v);
        size_t o = (size_t)slot * WSLOT + i;
        g_wh[o] = hi;
        g_wl[o] = __float2bfloat16(v - __bfloat162float(hi));
    }
}

__global__ void padzero_kernel() {
    int v = blockIdx.x, c = threadIdx.x;
    if (c < GDC - 456) {
        size_t o = (size_t)v * GDC + 456 + c;
        g_chi[o] = __float2bfloat16(0.f);
        g_clo[o] = __float2bfloat16(0.f);
    }
}

// ---------------- graph setup ----------------
__global__ void zero_deg_kernel() {
    int i = blockIdx.x * blockDim.x + threadIdx.x;
    if (i < NNODES) g_deg[i] = 0;
}

__global__ void count_deg_kernel(const int* __restrict__ dst) {
    for (int e = blockIdx.x * blockDim.x + threadIdx.x; e < NEDGES;
         e += gridDim.x * blockDim.x)
        atomicAdd(&g_deg[dst[e]], 1);
}

__global__ void scan1_kernel() {
    __shared__ int s[1024];
    int tid = threadIdx.x;
    int i = blockIdx.x * 1024 + tid;
    int v = (i < NNODES) ? g_deg[i] : 0;
    s[tid] = v;
    __syncthreads();
    for (int off = 1; off < 1024; off <<= 1) {
        int t = (tid >= off) ? s[tid - off] : 0;
        __syncthreads();
        s[tid] += t;
        __syncthreads();
    }
    if (i < NNODES) g_rowptr[i + 1] = s[tid];
    if (tid == 1023) g_bsum[blockIdx.x] = s[1023];
}

__global__ void scan2_kernel() {
    int acc = 0;
    for (int b = 0; b < 49; b++) { int t = g_bsum[b]; g_bsum[b] = acc; acc += t; }
}

__global__ void scan3_kernel() {
    int i = blockIdx.x * 1024 + threadIdx.x;
    if (i == 0) g_rowptr[0] = 0;
    if (i < NNODES) {
        int incl = g_rowptr[i + 1] + g_bsum[blockIdx.x];
        g_rowptr[i + 1] = incl;
        g_cur[i] = incl - g_deg[i];
        g_dis[i] = rsqrtf((float)(g_deg[i] + 1));
    }
}

__global__ void fill_csr_kernel(const int* __restrict__ src,
                                const int* __restrict__ dst) {
    for (int e = blockIdx.x * blockDim.x + threadIdx.x; e < NEDGES;
         e += gridDim.x * blockDim.x) {
        int d = dst[e];
        int p = atomicAdd(&g_cur[d], 1);
        g_colidx[p] = src[e];
    }
}

// ---------------- low-rank path ----------------
__global__ void zero_misc_kernel() {
    int i = blockIdx.x * blockDim.x + threadIdx.x;
    if (i < KLR * KLR) g_M[i] = 0.f;
    if (i < 2 * KLR)   g_cs[i] = 0.f;
    if (i < HD)        { g_mean[i] = 0.f; g_msq[i] = 0.f; }
}

__global__ void colsum_kernel() {
    int col = threadIdx.x;
    int r0 = blockIdx.x * 256;
    if (col < 2 * KLR) {
        float s = 0.f;
        int rend = min(r0 + 256, NNODES);
        for (int r = r0; r < rend; r++) s += g_t[(size_t)r * TD2 + col];
        atomicAdd(&g_cs[col], s);
    }
}

__global__ void nf_kernel() {
    int lane = threadIdx.x;
    float s = 0.f;
    for (int k = lane; k < KLR; k += 32) s += g_cs[k] * g_cs[KLR + k];
#pragma unroll
    for (int o = 16; o > 0; o >>= 1) s += __shfl_down_sync(0xffffffffu, s, o);
    if (lane == 0) g_inv_nf = 1.0f / (s / (float)NNODES + 1e-6f);
}

// M = V^T @ Z (100x100): 200 k-split blocks, 7x7 register tile per thread.
__global__ void __launch_bounds__(256) vtz_kernel() {
    __shared__ float Vs[32][112];
    __shared__ float Zs[32][112];
    const int tid = threadIdx.x;
    const int i = tid >> 4;
    const int j = tid & 15;
    const int kbeg = blockIdx.x * 250;
    const int kend = min(kbeg + 250, NNODES);

    float acc[7][7];
#pragma unroll
    for (int p = 0; p < 7; p++)
#pragma unroll
        for (int q = 0; q < 7; q++) acc[p][q] = 0.f;

    for (int k0 = kbeg; k0 < kend; k0 += 32) {
        int km = kend - k0;
        for (int idx = tid; idx < 32 * 112; idx += 256) {
            int kk = idx / 112, cc = idx - kk * 112;
            float v = 0.f, z = 0.f;
            if (kk < km && cc < KLR) {
                size_t b = (size_t)(k0 + kk) * TD2;
                v = g_t[b + KLR + cc];
                z = g_t[b + 2 * KLR + cc];
            }
            Vs[kk][cc] = v;
            Zs[kk][cc] = z;
        }
        __syncthreads();
#pragma unroll 4
        for (int kk = 0; kk < 32; kk++) {
            float av[7], bz[7];
#pragma unroll
            for (int p = 0; p < 7; p++) av[p] = Vs[kk][i + 16 * p];
#pragma unroll
            for (int q = 0; q < 7; q++) bz[q] = Zs[kk][j + 16 * q];
#pragma unroll
            for (int p = 0; p < 7; p++)
#pragma unroll
                for (int q = 0; q < 7; q++)
                    acc[p][q] = fmaf(av[p], bz[q], acc[p][q]);
        }
        __syncthreads();
    }
#pragma unroll
    for (int p = 0; p < 7; p++) {
        int r = i + 16 * p;
        if (r >= KLR) break;
#pragma unroll
        for (int q = 0; q < 7; q++) {
            int c = j + 16 * q;
            if (c < KLR) atomicAdd(&g_M[r * KLR + c], acc[p][q]);
        }
    }
}

// packed combine cols 0..199 = [res/nf | T] as bf16 hi/lo
__global__ void __launch_bounds__(256) respack_kernel() {
    __shared__ float Msh[KLR * KLR];
    __shared__ float Ush[16 * KLR];
    int tid = threadIdx.x;
    int r0 = blockIdx.x * 16;
    for (int idx = tid; idx < KLR * KLR; idx += 256) Msh[idx] = g_M[idx];
    for (int idx = tid; idx < 16 * KLR; idx += 256) {
        int r = idx / KLR, c = idx % KLR;
        Ush[idx] = (r0 + r < NNODES) ? g_t[(size_t)(r0 + r) * TD2 + c] : 0.f;
    }
    __syncthreads();
    float inv = g_inv_nf;
    int r = tid >> 4;
    int cg = tid & 15;
    if (r0 + r < NNODES) {
        float acc[7];
#pragma unroll
        for (int q = 0; q < 7; q++) acc[q] = 0.f;
        for (int k = 0; k < KLR; k++) {
            float a = Ush[r * KLR + k];
#pragma unroll
            for (int q = 0; q < 7; q++) {
                int c = cg + q * 16;
                if (c < KLR) acc[q] = fmaf(a, Msh[k * KLR + c], acc[q]);
            }
        }
        size_t base = (size_t)(r0 + r) * GDC;
#pragma unroll
        for (int q = 0; q < 7; q++) {
            int c = cg + q * 16;
            if (c < KLR) {
                float v = acc[q] * inv;
                __nv_bfloat16 hi = __float2bfloat16(v);
                g_chi[base + c] = hi;
                g_clo[base + c] = __float2bfloat16(v - __bfloat162float(hi));
            }
        }
#pragma unroll
        for (int q = 0; q < 7; q++) {
            int c = cg + q * 16;
            if (c < KLR) {
                float v = g_t[(size_t)(r0 + r) * TD2 + 3 * KLR + c];
                __nv_bfloat16 hi = __float2bfloat16(v);
                g_chi[base + KLR + c] = hi;
                g_clo[base + KLR + c] = __float2bfloat16(v - __bfloat162float(hi));
            }
        }
    }
}

// cols 200..455 of combine input = relu(aggregate + cb) as bf16 hi/lo
__global__ void agg_kernel(const float* __restrict__ cb) {
    __shared__ int   sh_u[64];
    __shared__ float sh_w[64];
    const int v = blockIdx.x;
    const int c = threadIdx.x;
    const float dv = g_dis[v];
    float acc = g_h[(size_t)v * HD + c] * dv * dv;
    const int s0 = g_rowptr[v], e0 = g_rowptr[v + 1];
    for (int s = s0; s < e0; s += 64) {
        int m = min(64, e0 - s);
        __syncthreads();
        if (c < m) {
            int u = g_colidx[s + c];
            sh_u[c] = u;
            sh_w[c] = g_dis[u] * dv;
        }
        __syncthreads();
        int j = 0;
        for (; j + 4 <= m; j += 4) {
            float h0 = g_h[(size_t)sh_u[j + 0] * HD + c];
            float h1 = g_h[(size_t)sh_u[j + 1] * HD + c];
            float h2 = g_h[(size_t)sh_u[j + 2] * HD + c];
            float h3 = g_h[(size_t)sh_u[j + 3] * HD + c];
            acc = fmaf(h0, sh_w[j + 0], acc);
            acc = fmaf(h1, sh_w[j + 1], acc);
            acc = fmaf(h2, sh_w[j + 2], acc);
            acc = fmaf(h3, sh_w[j + 3], acc);
        }
        for (; j < m; j++)
            acc = fmaf(g_h[(size_t)sh_u[j] * HD + c], sh_w[j], acc);
    }
    acc = fmaxf(acc + cb[c], 0.f);
    __nv_bfloat16 hi = __float2bfloat16(acc);
    size_t o = (size_t)v * GDC + 200 + c;
    g_chi[o] = hi;
    g_clo[o] = __float2bfloat16(acc - __bfloat162float(hi));
}

// ---------------- batch norm ----------------
__global__ void bn_stats_kernel() {
    int col = threadIdx.x;
    int r0 = blockIdx.x * 128;
    int rend = min(r0 + 128, NNODES);
    float s = 0.f, s2 = 0.f;
    for (int r = r0; r < rend; r++) {
        float v = g_x[(size_t)r * HD + col];
        s += v;
        s2 = fmaf(v, v, s2);
    }
    atomicAdd(&g_mean[col], s);
    atomicAdd(&g_msq[col], s2);
}

__global__ void bn_final_kernel(const float* __restrict__ gam,
                                const float* __restrict__ bet) {
    int c = threadIdx.x;
    float m = g_mean[c] / (float)NNODES;
    float var = g_msq[c] / (float)NNODES - m * m;
    float sc = gam[c] * rsqrtf(var + 1e-5f);
    g_scale[c] = sc;
    g_shift[c] = bet[c] - m * sc;
}

__global__ void bn_apply_kernel() {
    size_t i = (size_t)blockIdx.x * blockDim.x + threadIdx.x;
    if (i < (size_t)NNODES * HD) {
        int c = (int)(i & (HD - 1));
        float v = fmaf(g_x[i], g_scale[c], g_shift[c]);
        g_x[i] = v;
        __nv_bfloat16 hi = __float2bfloat16(v);
        g_xhi[i] = hi;
        g_xlo[i] = __float2bfloat16(v - __bfloat162float(hi));
    }
}

// ---------------- host orchestration ----------------
extern "C" void kernel_launch(void* const* d_in, const int* in_sizes, int n_in,
                              void* d_out, int out_size) {
    (void)in_sizes; (void)n_in; (void)out_size;
    const float* x_in = (const float*)d_in[0];
    const int*   ei   = (const int*)d_in[1];
    const int*   src  = ei;
    const int*   dst  = ei + NEDGES;

    const float* cw[3] = {(const float*)d_in[2],  (const float*)d_in[8],  (const float*)d_in[14]};
    const float* cb[3] = {(const float*)d_in[3],  (const float*)d_in[9],  (const float*)d_in[15]};
    const float* aw[3] = {(const float*)d_in[4],  (const float*)d_in[10], (const float*)d_in[16]};
    const float* ab[3] = {(const float*)d_in[5],  (const float*)d_in[11], (const float*)d_in[17]};
    const float* rw[3] = {(const float*)d_in[6],  (const float*)d_in[12], (const float*)d_in[18]};
    const float* rb[3] = {(const float*)d_in[7],  (const float*)d_in[13], (const float*)d_in[19]};
    const float* gam[2] = {(const float*)d_in[20], (const float*)d_in[22]};
    const float* bet[2] = {(const float*)d_in[21], (const float*)d_in[23]};
    float* out = (float*)d_out;

    float *p_x, *p_h, *p_t;
    __nv_bfloat16 *p_xhi, *p_xlo, *p_chi, *p_clo, *p_wh, *p_wl;
    cudaGetSymbolAddress((void**)&p_x, g_x);
    cudaGetSymbolAddress((void**)&p_h, g_h);
    cudaGetSymbolAddress((void**)&p_t, g_t);
    cudaGetSymbolAddress((void**)&p_xhi, g_xhi);
    cudaGetSymbolAddress((void**)&p_xlo, g_xlo);
    cudaGetSymbolAddress((void**)&p_chi, g_chi);
    cudaGetSymbolAddress((void**)&p_clo, g_clo);
    cudaGetSymbolAddress((void**)&p_wh, g_wh);
    cudaGetSymbolAddress((void**)&p_wl, g_wl);

    const int SMB = 2 * STAGE_BYTES + 1024;

    static cudaStream_t s2 = nullptr, s3 = nullptr;
    static cudaEvent_t evFork = nullptr, evH = nullptr, evAgg = nullptr;
    static cudaEvent_t evT = nullptr, evNF = nullptr, evW = nullptr;
    if (s2 == nullptr) {
        cudaFuncSetAttribute(mma_gemm, cudaFuncAttributeMaxDynamicSharedMemorySize, SMB);
        cudaStreamCreateWithFlags(&s2, cudaStreamNonBlocking);
        cudaStreamCreateWithFlags(&s3, cudaStreamNonBlocking);
        cudaEventCreateWithFlags(&evFork, cudaEventDisableTiming);
        cudaEventCreateWithFlags(&evH, cudaEventDisableTiming);
        cudaEventCreateWithFlags(&evAgg, cudaEventDisableTiming);
        cudaEventCreateWithFlags(&evT, cudaEventDisableTiming);
        cudaEventCreateWithFlags(&evNF, cudaEventDisableTiming);
        cudaEventCreateWithFlags(&evW, cudaEventDisableTiming);
    }

    // weight slots: 3l=cw, 3l+1=aw, 3l+2=rw; stored [Nout x Kpad]
    const int wK[9]    = {128, 128, 456, 256, 256, 456, 256, 256, 456};
    const int wN[9]    = {256, 400, 256, 256, 400, 256, 256, 400, 128};
    const int wNout[9] = {256, 448, 256, 256, 448, 256, 256, 448, 128};
    const int wKpad[9] = {128, 128, 512, 256, 256, 512, 256, 256, 512};
    const float* wptr[9] = {cw[0], aw[0], rw[0], cw[1], aw[1], rw[1],
                            cw[2], aw[2], rw[2]};

    // ---- fork: CSR setup on s2, weight pre-split on s3 ----
    cudaEventRecord(evFork, 0);
    cudaStreamWaitEvent(s2, evFork, 0);
    cudaStreamWaitEvent(s3, evFork, 0);

    padzero_kernel<<<NNODES, 64, 0, s2>>>();
    zero_deg_kernel<<<(NNODES + 255) / 256, 256, 0, s2>>>();
    count_deg_kernel<<<800, 256, 0, s2>>>(dst);
    scan1_kernel<<<49, 1024, 0, s2>>>();
    scan2_kernel<<<1, 1, 0, s2>>>();
    scan3_kernel<<<49, 1024, 0, s2>>>();
    fill_csr_kernel<<<800, 256, 0, s2>>>(src, dst);

    for (int w = 0; w < 9; w++) {
        int n = wNout[w] * wKpad[w];
        wsplit_kernel<<<(n + 255) / 256, 256, 0, s3>>>(
            wptr[w], wK[w], wN[w], wNout[w], wKpad[w], w);
    }
    cudaEventRecord(evW, s3);

    // ---- main stream: input conversion, then wait for weights ----
    xsplit_kernel<<<(NNODES * 128 + 255) / 256, 256>>>(x_in, (long)NNODES * 128);
    cudaStreamWaitEvent(0, evW, 0);

    int din = 128;
    for (int l = 0; l < 3; l++) {
        const __nv_bfloat16* cwh = p_wh + (size_t)(3 * l) * WSLOT;
        const __nv_bfloat16* cwl = p_wl + (size_t)(3 * l) * WSLOT;
        const __nv_bfloat16* awh = p_wh + (size_t)(3 * l + 1) * WSLOT;
        const __nv_bfloat16* awl = p_wl + (size_t)(3 * l + 1) * WSLOT;
        const __nv_bfloat16* rwh = p_wh + (size_t)(3 * l + 2) * WSLOT;
        const __nv_bfloat16* rwl = p_wl + (size_t)(3 * l + 2) * WSLOT;

        // h = x @ cw  (main)
        mma_gemm<<<dim3(HD / 64, MB), 256, SMB>>>(
            p_xhi, p_xlo, cwh, cwl, nullptr, p_h, NNODES, din, HD, HD, 0);
        cudaEventRecord(evH, 0);

        // side stream: aggregation overlaps t-GEMM
        cudaStreamWaitEvent(s2, evH, 0);
        agg_kernel<<<NNODES, HD, 0, s2>>>(cb[l]);
        cudaEventRecord(evAgg, s2);

        // main: zero accumulators, then t = relu(x @ aw + ab), 7 col tiles
        zero_misc_kernel<<<(KLR * KLR + 255) / 256, 256>>>();
        mma_gemm<<<dim3(7, MB), 256, SMB>>>(
            p_xhi, p_xlo, awh, awl, ab[l], p_t, NNODES, din, TD2, 400, 1);
        cudaEventRecord(evT, 0);

        // side stream: colsum + nf overlap vtz on main
        cudaStreamWaitEvent(s2, evT, 0);
        colsum_kernel<<<(NNODES + 255) / 256, 256, 0, s2>>>();
        nf_kernel<<<1, 32, 0, s2>>>();
        cudaEventRecord(evNF, s2);

        // main: vtz, then respack (needs nf + M)
        vtz_kernel<<<200, 256>>>();
        cudaStreamWaitEvent(0, evNF, 0);
        respack_kernel<<<NNODES / 16, 256>>>();

        // join: combine needs agg output
        cudaStreamWaitEvent(0, evAgg, 0);
        if (l < 2) {
            mma_gemm<<<dim3(HD / 64, MB), 256, SMB>>>(
                p_chi, p_clo, rwh, rwl, rb[l], p_x, NNODES, GDC, HD, HD, 1);
            bn_stats_kernel<<<(NNODES + 127) / 128, 256>>>();
            bn_final_kernel<<<1, HD>>>(gam[l], bet[l]);
            bn_apply_kernel<<<(NNODES * HD + 255) / 256, 256>>>();
            din = HD;
        } else {
            mma_gemm<<<dim3(2, MB), 256, SMB>>>(
                p_chi, p_clo, rwh, rwl, rb[l], out, NNODES, GDC, 128, 128, 0);
        }
    }
}

// round 10
// speedup vs baseline: 1.0437x; 1.0274x over previous
#include <cuda_runtime.h>
#include <cuda_bf16.h>
#include <cstdint>

// ---------------- problem constants ----------------
#define NNODES 50000
#define NEDGES 800000
#define HD     256      // hidden width
#define TD2    512      // padded 4*K (row stride of g_t)
#define GDC    512      // padded combine K (456 -> 512)
#define KLR    100
#define MB     391      // ceil(50000/128)
#define WSLOT  (512 * 512)

// ---------------- static scratch ----------------
__device__ float g_x[NNODES * HD];
__device__ float g_h[NNODES * HD];
__device__ float g_t[NNODES * TD2];
__device__ __nv_bfloat16 g_xhi[NNODES * HD];
__device__ __nv_bfloat16 g_xlo[NNODES * HD];
__device__ __nv_bfloat16 g_chi[NNODES * GDC];
__device__ __nv_bfloat16 g_clo[NNODES * GDC];
__device__ __nv_bfloat16 g_wh[9 * WSLOT];
__device__ __nv_bfloat16 g_wl[9 * WSLOT];
__device__ float g_M[KLR * KLR];
__device__ float g_cs[2 * KLR];
__device__ float g_inv_nf;
__device__ float g_mean[HD];
__device__ float g_msq[HD];
__device__ float g_scale[HD];
__device__ float g_shift[HD];
__device__ float g_dis[NNODES];
__device__ int   g_deg[NNODES];
__device__ int   g_rowptr[NNODES + 1];
__device__ int   g_cur[NNODES];
__device__ int   g_colidx[NEDGES];
__device__ int   g_bsum[64];

// ---------------- PTX helpers ----------------
__device__ __forceinline__ uint32_t smem_u32(const void* p) {
    uint32_t a;
    asm("{ .reg .u64 t; cvta.to.shared.u64 t, %1; cvt.u32.u64 %0, t; }"
        : "=r"(a) : "l"(p));
    return a;
}

__device__ __forceinline__ void cp16(uint32_t dst, const void* src, int sz) {
    asm volatile("cp.async.cg.shared.global [%0], [%1], 16, %2;"
                 :: "r"(dst), "l"(src), "r"(sz) : "memory");
}

__device__ __forceinline__ void ldm_x4(uint32_t* r, uint32_t addr) {
    asm volatile("ldmatrix.sync.aligned.m8n8.x4.shared.b16 {%0,%1,%2,%3}, [%4];"
                 : "=r"(r[0]), "=r"(r[1]), "=r"(r[2]), "=r"(r[3]) : "r"(addr));
}

__device__ __forceinline__ void mma_bf16(float* d, const uint32_t* a,
                                         const uint32_t* b) {
    asm volatile(
        "mma.sync.aligned.m16n8k16.row.col.f32.bf16.bf16.f32 "
        "{%0,%1,%2,%3}, {%4,%5,%6,%7}, {%8,%9}, {%0,%1,%2,%3};"
        : "+f"(d[0]), "+f"(d[1]), "+f"(d[2]), "+f"(d[3])
        : "r"(a[0]), "r"(a[1]), "r"(a[2]), "r"(a[3]), "r"(b[0]), "r"(b[1]));
}

// ---------------- shared GEMM mainloop (round-6 proven config) ----------------
#define STAGE_BYTES 49152

#define GEMM_MAINLOOP(ACC)                                                     \
    extern __shared__ char dsm_raw[];                                          \
    uint32_t base0 = (smem_u32(dsm_raw) + 1023u) & ~1023u;                     \
    const int tid = threadIdx.x;                                               \
    const int wid = tid >> 5;                                                  \
    const int lane = tid & 31;                                                 \
    const int wm = wid & 3;                                                    \
    const int wn = wid >> 2;                                                   \
    const int row0 = blockIdx.y * 128;                                         \
    const int col0 = blockIdx.x * 64;                                          \
    const __nv_bfloat16* Bh0 = Bh + (size_t)col0 * K;                          \
    const __nv_bfloat16* Bl0 = Bl + (size_t)col0 * K;                          \
    const int nc = K >> 6;                                                     \
    float ACC[2][4][4];                                                        \
    _Pragma("unroll")                                                          \
    for (int mt = 0; mt < 2; mt++)                                             \
        _Pragma("unroll")                                                      \
        for (int nt = 0; nt < 4; nt++)                                         \
            _Pragma("unroll")                                                  \
            for (int q = 0; q < 4; q++) ACC[mt][nt][q] = 0.f;                  \
    auto load_chunk = [&](int c) {                                             \
        uint32_t sb = base0 + (uint32_t)(c & 1) * STAGE_BYTES;                 \
        int k0 = c << 6;                                                       \
        _Pragma("unroll 4")                                                    \
        for (int j = 0; j < 4; j++) {                                          \
            int i = tid + j * 256;                                             \
            int r = i >> 3, seg = i & 7;                                       \
            int off = r * 128 + seg * 16;                                      \
            uint32_t sw = (uint32_t)(off ^ ((off >> 3) & 0x70));               \
            int ga = row0 + r;                                                 \
            int ok = (ga < M) ? 16 : 0;                                        \
            if (ga >= M) ga = 0;                                               \
            size_t ao = (size_t)ga * K + k0 + seg * 8;                         \
            cp16(sb + sw,         Ah + ao, ok);                                \
            cp16(sb + 16384 + sw, Al + ao, ok);                                \
        }                                                                      \
        {                                                                      \
            int i = tid;                                                       \
            int r = i >> 3, seg = i & 7;                                       \
            int off = r * 128 + seg * 16;                                      \
            uint32_t sw = (uint32_t)(off ^ ((off >> 3) & 0x70));               \
            size_t bo = (size_t)r * K + k0 + seg * 8;                          \
            cp16(sb + 32768 + sw, Bh0 + bo, 16);                               \
            cp16(sb + 40960 + sw, Bl0 + bo, 16);                               \
        }                                                                      \
        {                                                                      \
            int i = tid + 256;                                                 \
            int r = i >> 3, seg = i & 7;                                       \
            int off = r * 128 + seg * 16;                                      \
            uint32_t sw = (uint32_t)(off ^ ((off >> 3) & 0x70));               \
            size_t bo = (size_t)r * K + k0 + seg * 8;                          \
            cp16(sb + 32768 + sw, Bh0 + bo, 16);                               \
            cp16(sb + 40960 + sw, Bl0 + bo, 16);                               \
        }                                                                      \
        asm volatile("cp.async.commit_group;" ::: "memory");                   \
    };                                                                         \
    const int a_off0 = (wm * 32 + (lane & 15)) * 128 + ((lane >> 4) << 4);     \
    const int b_off0 = (wn * 32 + ((lane >> 4) << 3) + (lane & 7)) * 128       \
                     + (((lane >> 3) & 1) << 4);                               \
    load_chunk(0);                                                             \
    for (int c = 0; c < nc; c++) {                                             \
        if (c + 1 < nc) {                                                      \
            load_chunk(c + 1);                                                 \
            asm volatile("cp.async.wait_group 1;" ::: "memory");               \
        } else {                                                               \
            asm volatile("cp.async.wait_group 0;" ::: "memory");               \
        }                                                                      \
        __syncthreads();                                                       \
        uint32_t sb = base0 + (uint32_t)(c & 1) * STAGE_BYTES;                 \
        _Pragma("unroll")                                                      \
        for (int kk = 0; kk < 4; kk++) {                                       \
            uint32_t ah[2][4], al[2][4], bh[2][4], bl[2][4];                   \
            _Pragma("unroll")                                                  \
            for (int mt = 0; mt < 2; mt++) {                                   \
                int off = a_off0 + mt * 2048 + kk * 32;                        \
                uint32_t sw = (uint32_t)(off ^ ((off >> 3) & 0x70));           \
                ldm_x4(ah[mt], sb + sw);                                       \
                ldm_x4(al[mt], sb + 16384 + sw);                               \
            }                                                                  \
            _Pragma("unroll")                                                  \
            for (int np = 0; np < 2; np++) {                                   \
                int off = b_off0 + np * 2048 + kk * 32;                        \
                uint32_t sw = (uint32_t)(off ^ ((off >> 3) & 0x70));           \
                ldm_x4(bh[np], sb + 32768 + sw);                               \
                ldm_x4(bl[np], sb + 40960 + sw);                               \
            }                                                                  \
            _Pragma("unroll")                                                  \
            for (int mt = 0; mt < 2; mt++)                                     \
                _Pragma("unroll")                                              \
                for (int nt = 0; nt < 4; nt++) {                               \
                    const uint32_t* bhp = &bh[nt >> 1][(nt & 1) * 2];          \
                    const uint32_t* blp = &bl[nt >> 1][(nt & 1) * 2];          \
                    mma_bf16(ACC[mt][nt], ah[mt], bhp);                        \
                    mma_bf16(ACC[mt][nt], ah[mt], blp);                        \
                    mma_bf16(ACC[mt][nt], al[mt], bhp);                        \
                }                                                              \
        }                                                                      \
        __syncthreads();                                                       \
    }

// ---------------- plain GEMM: C = act(A@B^T + bias) ----------------
__global__ void __launch_bounds__(256, 2)
mma_gemm(const __nv_bfloat16* __restrict__ Ah, const __nv_bfloat16* __restrict__ Al,
         const __nv_bfloat16* __restrict__ Bh, const __nv_bfloat16* __restrict__ Bl,
         const float* __restrict__ bias, float* __restrict__ C,
         int M, int K, int ldc, int nvalid, int relu) {
    GEMM_MAINLOOP(acc)
#pragma unroll
    for (int mt = 0; mt < 2; mt++) {
        int ra = row0 + wm * 32 + mt * 16 + (lane >> 2);
        int rb = ra + 8;
#pragma unroll
        for (int nt = 0; nt < 4; nt++) {
            int c0 = col0 + wn * 32 + nt * 8 + (lane & 3) * 2;
            float bv0 = 0.f, bv1 = 0.f;
            if (bias && c0 < nvalid) {
                bv0 = __ldg(&bias[c0]);
                bv1 = __ldg(&bias[c0 + 1]);
            }
            float v0 = acc[mt][nt][0] + bv0;
            float v1 = acc[mt][nt][1] + bv1;
            float v2 = acc[mt][nt][2] + bv0;
            float v3 = acc[mt][nt][3] + bv1;
            if (relu) {
                v0 = fmaxf(v0, 0.f); v1 = fmaxf(v1, 0.f);
                v2 = fmaxf(v2, 0.f); v3 = fmaxf(v3, 0.f);
            }
            if (ra < M) *(float2*)&C[(size_t)ra * ldc + c0] = make_float2(v0, v1);
            if (rb < M) *(float2*)&C[(size_t)rb * ldc + c0] = make_float2(v2, v3);
        }
    }
}

// ---------------- fused h+t GEMM ----------------
// B slot rows: [0,256) = cw cols -> C1 (g_h, no bias/relu);
//              [256,704) = aw cols -> C2 (g_t, +bias2, relu, nvalid 400).
__global__ void __launch_bounds__(256, 2)
mma_gemm_fused(const __nv_bfloat16* __restrict__ Ah, const __nv_bfloat16* __restrict__ Al,
               const __nv_bfloat16* __restrict__ Bh, const __nv_bfloat16* __restrict__ Bl,
               const float* __restrict__ bias2,
               float* __restrict__ C1, float* __restrict__ C2,
               int M, int K) {
    GEMM_MAINLOOP(acc)
    float* C;
    int ldc, rel, cbase, nval;
    const float* bias;
    if (col0 < 256) {
        C = C1; ldc = HD; rel = 0; bias = nullptr; cbase = col0; nval = HD;
    } else {
        C = C2; ldc = TD2; rel = 1; bias = bias2; cbase = col0 - 256; nval = 400;
    }
#pragma unroll
    for (int mt = 0; mt < 2; mt++) {
        int ra = row0 + wm * 32 + mt * 16 + (lane >> 2);
        int rb = ra + 8;
#pragma unroll
        for (int nt = 0; nt < 4; nt++) {
            int c0 = cbase + wn * 32 + nt * 8 + (lane & 3) * 2;
            float bv0 = 0.f, bv1 = 0.f;
            if (bias && c0 < nval) {
                bv0 = __ldg(&bias[c0]);
                bv1 = __ldg(&bias[c0 + 1]);
            }
            float v0 = acc[mt][nt][0] + bv0;
            float v1 = acc[mt][nt][1] + bv1;
            float v2 = acc[mt][nt][2] + bv0;
            float v3 = acc[mt][nt][3] + bv1;
            if (rel) {
                v0 = fmaxf(v0, 0.f); v1 = fmaxf(v1, 0.f);
                v2 = fmaxf(v2, 0.f); v3 = fmaxf(v3, 0.f);
            }
            if (ra < M) *(float2*)&C[(size_t)ra * ldc + c0] = make_float2(v0, v1);
            if (rb < M) *(float2*)&C[(size_t)rb * ldc + c0] = make_float2(v2, v3);
        }
    }
}

// ---------------- conversion kernels ----------------
__global__ void xsplit_kernel(const float* __restrict__ x, long n) {
    long i = (long)blockIdx.x * blockDim.x + threadIdx.x;
    if (i < n) {
        float v = x[i];
        __nv_bfloat16 hi = __float2bfloat16(v);
        g_xhi[i] = hi;
        g_xlo[i] = __float2bfloat16(v - __bfloat162float(hi));
    }
}

// W[K x N] fp32 -> transposed padded bf16 split into slot rows [row0, row0+Nout)
__global__ void wsplit_kernel(const float* __restrict__ W, int K, int N,
                              int Nout, int Kpad, int slot, int row0) {
    int i = blockIdx.x * blockDim.x + threadIdx.x;
    if (i < Nout * Kpad) {
        int n = i / Kpad, k = i - n * Kpad;
        float v = (n < N && k < K) ? W[(size_t)k * N + n] : 0.f;
        __nv_bfloat16 hi = __float2bfloat16(v);
        size_t o = (size_t)slot * WSLOT + (size_t)(row0 + n) * Kpad + k;
        g_wh[o] = hi;
        g_wl[o] = __float2bfloat16(v - __bfloat162float(hi));
    }
}

__global__ void padzero_kernel() {
    int v = blockIdx.x, c = threadIdx.x;
    if (c < GDC - 456) {
        size_t o = (size_t)v * GDC + 456 + c;
        g_chi[o] = __float2bfloat16(0.f);
        g_clo[o] = __float2bfloat16(0.f);
    }
}

// ---------------- graph setup ----------------
__global__ void zero_deg_kernel() {
    int i = blockIdx.x * blockDim.x + threadIdx.x;
    if (i < NNODES) g_deg[i] = 0;
}

__global__ void count_deg_kernel(const int* __restrict__ dst) {
    for (int e = blockIdx.x * blockDim.x + threadIdx.x; e < NEDGES;
         e += gridDim.x * blockDim.x)
        atomicAdd(&g_deg[dst[e]], 1);
}

__global__ void scan1_kernel() {
    __shared__ int s[1024];
    int tid = threadIdx.x;
    int i = blockIdx.x * 1024 + tid;
    int v = (i < NNODES) ? g_deg[i] : 0;
    s[tid] = v;
    __syncthreads();
    for (int off = 1; off < 1024; off <<= 1) {
        int t = (tid >= off) ? s[tid - off] : 0;
        __syncthreads();
        s[tid] += t;
        __syncthreads();
    }
    if (i < NNODES) g_rowptr[i + 1] = s[tid];
    if (tid == 1023) g_bsum[blockIdx.x] = s[1023];
}

__global__ void scan2_kernel() {
    int acc = 0;
    for (int b = 0; b < 49; b++) { int t = g_bsum[b]; g_bsum[b] = acc; acc += t; }
}

__global__ void scan3_kernel() {
    int i = blockIdx.x * 1024 + threadIdx.x;
    if (i == 0) g_rowptr[0] = 0;
    if (i < NNODES) {
        int incl = g_rowptr[i + 1] + g_bsum[blockIdx.x];
        g_rowptr[i + 1] = incl;
        g_cur[i] = incl - g_deg[i];
        g_dis[i] = rsqrtf((float)(g_deg[i] + 1));
    }
}

__global__ void fill_csr_kernel(const int* __restrict__ src,
                                const int* __restrict__ dst) {
    for (int e = blockIdx.x * blockDim.x + threadIdx.x; e < NEDGES;
         e += gridDim.x * blockDim.x) {
        int d = dst[e];
        int p = atomicAdd(&g_cur[d], 1);
        g_colidx[p] = src[e];
    }
}

// ---------------- low-rank path ----------------
__global__ void zero_misc_kernel() {
    int i = blockIdx.x * blockDim.x + threadIdx.x;
    if (i < KLR * KLR) g_M[i] = 0.f;
    if (i < 2 * KLR)   g_cs[i] = 0.f;
    if (i < HD)        { g_mean[i] = 0.f; g_msq[i] = 0.f; }
}

__global__ void colsum_kernel() {
    int col = threadIdx.x;
    int r0 = blockIdx.x * 256;
    if (col < 2 * KLR) {
        float s = 0.f;
        int rend = min(r0 + 256, NNODES);
        for (int r = r0; r < rend; r++) s += g_t[(size_t)r * TD2 + col];
        atomicAdd(&g_cs[col], s);
    }
}

__global__ void nf_kernel() {
    int lane = threadIdx.x;
    float s = 0.f;
    for (int k = lane; k < KLR; k += 32) s += g_cs[k] * g_cs[KLR + k];
#pragma unroll
    for (int o = 16; o > 0; o >>= 1) s += __shfl_down_sync(0xffffffffu, s, o);
    if (lane == 0) g_inv_nf = 1.0f / (s / (float)NNODES + 1e-6f);
}

// M = V^T @ Z (100x100): 200 k-split blocks, 7x7 register tile per thread.
__global__ void __launch_bounds__(256) vtz_kernel() {
    __shared__ float Vs[32][112];
    __shared__ float Zs[32][112];
    const int tid = threadIdx.x;
    const int i = tid >> 4;
    const int j = tid & 15;
    const int kbeg = blockIdx.x * 250;
    const int kend = min(kbeg + 250, NNODES);

    float acc[7][7];
#pragma unroll
    for (int p = 0; p < 7; p++)
#pragma unroll
        for (int q = 0; q < 7; q++) acc[p][q] = 0.f;

    for (int k0 = kbeg; k0 < kend; k0 += 32) {
        int km = kend - k0;
        for (int idx = tid; idx < 32 * 112; idx += 256) {
            int kk = idx / 112, cc = idx - kk * 112;
            float v = 0.f, z = 0.f;
            if (kk < km && cc < KLR) {
                size_t b = (size_t)(k0 + kk) * TD2;
                v = g_t[b + KLR + cc];
                z = g_t[b + 2 * KLR + cc];
            }
            Vs[kk][cc] = v;
            Zs[kk][cc] = z;
        }
        __syncthreads();
#pragma unroll 4
        for (int kk = 0; kk < 32; kk++) {
            float av[7], bz[7];
#pragma unroll
            for (int p = 0; p < 7; p++) av[p] = Vs[kk][i + 16 * p];
#pragma unroll
            for (int q = 0; q < 7; q++) bz[q] = Zs[kk][j + 16 * q];
#pragma unroll
            for (int p = 0; p < 7; p++)
#pragma unroll
                for (int q = 0; q < 7; q++)
                    acc[p][q] = fmaf(av[p], bz[q], acc[p][q]);
        }
        __syncthreads();
    }
#pragma unroll
    for (int p = 0; p < 7; p++) {
        int r = i + 16 * p;
        if (r >= KLR) break;
#pragma unroll
        for (int q = 0; q < 7; q++) {
            int c = j + 16 * q;
            if (c < KLR) atomicAdd(&g_M[r * KLR + c], acc[p][q]);
        }
    }
}

// packed combine cols 0..199 = [res/nf | T] as bf16 hi/lo
__global__ void __launch_bounds__(256) respack_kernel() {
    __shared__ float Msh[KLR * KLR];
    __shared__ float Ush[16 * KLR];
    int tid = threadIdx.x;
    int r0 = blockIdx.x * 16;
    for (int idx = tid; idx < KLR * KLR; idx += 256) Msh[idx] = g_M[idx];
    for (int idx = tid; idx < 16 * KLR; idx += 256) {
        int r = idx / KLR, c = idx % KLR;
        Ush[idx] = (r0 + r < NNODES) ? g_t[(size_t)(r0 + r) * TD2 + c] : 0.f;
    }
    __syncthreads();
    float inv = g_inv_nf;
    int r = tid >> 4;
    int cg = tid & 15;
    if (r0 + r < NNODES) {
        float acc[7];
#pragma unroll
        for (int q = 0; q < 7; q++) acc[q] = 0.f;
        for (int k = 0; k < KLR; k++) {
            float a = Ush[r * KLR + k];
#pragma unroll
            for (int q = 0; q < 7; q++) {
                int c = cg + q * 16;
                if (c < KLR) acc[q] = fmaf(a, Msh[k * KLR + c], acc[q]);
            }
        }
        size_t base = (size_t)(r0 + r) * GDC;
#pragma unroll
        for (int q = 0; q < 7; q++) {
            int c = cg + q * 16;
            if (c < KLR) {
                float v = acc[q] * inv;
                __nv_bfloat16 hi = __float2bfloat16(v);
                g_chi[base + c] = hi;
                g_clo[base + c] = __float2bfloat16(v - __bfloat162float(hi));
            }
        }
#pragma unroll
        for (int q = 0; q < 7; q++) {
            int c = cg + q * 16;
            if (c < KLR) {
                float v = g_t[(size_t)(r0 + r) * TD2 + 3 * KLR + c];
                __nv_bfloat16 hi = __float2bfloat16(v);
                g_chi[base + KLR + c] = hi;
                g_clo[base + KLR + c] = __float2bfloat16(v - __bfloat162float(hi));
            }
        }
    }
}

// cols 200..455 of combine input = relu(aggregate + cb) as bf16 hi/lo
__global__ void agg_kernel(const float* __restrict__ cb) {
    __shared__ int   sh_u[64];
    __shared__ float sh_w[64];
    const int v = blockIdx.x;
    const int c = threadIdx.x;
    const float dv = g_dis[v];
    float acc = g_h[(size_t)v * HD + c] * dv * dv;
    const int s0 = g_rowptr[v], e0 = g_rowptr[v + 1];
    for (int s = s0; s < e0; s += 64) {
        int m = min(64, e0 - s);
        __syncthreads();
        if (c < m) {
            int u = g_colidx[s + c];
            sh_u[c] = u;
            sh_w[c] = g_dis[u] * dv;
        }
        __syncthreads();
        int j = 0;
        for (; j + 4 <= m; j += 4) {
            float h0 = g_h[(size_t)sh_u[j + 0] * HD + c];
            float h1 = g_h[(size_t)sh_u[j + 1] * HD + c];
            float h2 = g_h[(size_t)sh_u[j + 2] * HD + c];
            float h3 = g_h[(size_t)sh_u[j + 3] * HD + c];
            acc = fmaf(h0, sh_w[j + 0], acc);
            acc = fmaf(h1, sh_w[j + 1], acc);
            acc = fmaf(h2, sh_w[j + 2], acc);
            acc = fmaf(h3, sh_w[j + 3], acc);
        }
        for (; j < m; j++)
            acc = fmaf(g_h[(size_t)sh_u[j] * HD + c], sh_w[j], acc);
    }
    acc = fmaxf(acc + cb[c], 0.f);
    __nv_bfloat16 hi = __float2bfloat16(acc);
    size_t o = (size_t)v * GDC + 200 + c;
    g_chi[o] = hi;
    g_clo[o] = __float2bfloat16(acc - __bfloat162float(hi));
}

// ---------------- batch norm ----------------
__global__ void bn_stats_kernel() {
    int col = threadIdx.x;
    int r0 = blockIdx.x * 128;
    int rend = min(r0 + 128, NNODES);
    float s = 0.f, s2 = 0.f;
    for (int r = r0; r < rend; r++) {
        float v = g_x[(size_t)r * HD + col];
        s += v;
        s2 = fmaf(v, v, s2);
    }
    atomicAdd(&g_mean[col], s);
    atomicAdd(&g_msq[col], s2);
}

__global__ void bn_final_kernel(const float* __restrict__ gam,
                                const float* __restrict__ bet) {
    int c = threadIdx.x;
    float m = g_mean[c] / (float)NNODES;
    float var = g_msq[c] / (float)NNODES - m * m;
    float sc = gam[c] * rsqrtf(var + 1e-5f);
    g_scale[c] = sc;
    g_shift[c] = bet[c] - m * sc;
}

// post-BN x only consumed as bf16 hi/lo -> no fp32 writeback
__global__ void bn_apply_kernel() {
    size_t i = (size_t)blockIdx.x * blockDim.x + threadIdx.x;
    if (i < (size_t)NNODES * HD) {
        int c = (int)(i & (HD - 1));
        float v = fmaf(g_x[i], g_scale[c], g_shift[c]);
        __nv_bfloat16 hi = __float2bfloat16(v);
        g_xhi[i] = hi;
        g_xlo[i] = __float2bfloat16(v - __bfloat162float(hi));
    }
}

// ---------------- host orchestration ----------------
extern "C" void kernel_launch(void* const* d_in, const int* in_sizes, int n_in,
                              void* d_out, int out_size) {
    (void)in_sizes; (void)n_in; (void)out_size;
    const float* x_in = (const float*)d_in[0];
    const int*   ei   = (const int*)d_in[1];
    const int*   src  = ei;
    const int*   dst  = ei + NEDGES;

    const float* cw[3] = {(const float*)d_in[2],  (const float*)d_in[8],  (const float*)d_in[14]};
    const float* cb[3] = {(const float*)d_in[3],  (const float*)d_in[9],  (const float*)d_in[15]};
    const float* aw[3] = {(const float*)d_in[4],  (const float*)d_in[10], (const float*)d_in[16]};
    const float* ab[3] = {(const float*)d_in[5],  (const float*)d_in[11], (const float*)d_in[17]};
    const float* rw[3] = {(const float*)d_in[6],  (const float*)d_in[12], (const float*)d_in[18]};
    const float* rb[3] = {(const float*)d_in[7],  (const float*)d_in[13], (const float*)d_in[19]};
    const float* gam[2] = {(const float*)d_in[20], (const float*)d_in[22]};
    const float* bet[2] = {(const float*)d_in[21], (const float*)d_in[23]};
    float* out = (float*)d_out;

    float *p_x, *p_h, *p_t;
    __nv_bfloat16 *p_xhi, *p_xlo, *p_chi, *p_clo, *p_wh, *p_wl;
    cudaGetSymbolAddress((void**)&p_x, g_x);
    cudaGetSymbolAddress((void**)&p_h, g_h);
    cudaGetSymbolAddress((void**)&p_t, g_t);
    cudaGetSymbolAddress((void**)&p_xhi, g_xhi);
    cudaGetSymbolAddress((void**)&p_xlo, g_xlo);
    cudaGetSymbolAddress((void**)&p_chi, g_chi);
    cudaGetSymbolAddress((void**)&p_clo, g_clo);
    cudaGetSymbolAddress((void**)&p_wh, g_wh);
    cudaGetSymbolAddress((void**)&p_wl, g_wl);

    const int SMB = 2 * STAGE_BYTES + 1024;

    static cudaStream_t s2 = nullptr, s3 = nullptr;
    static cudaEvent_t evFork = nullptr, evH = nullptr, evAgg = nullptr;
    static cudaEvent_t evW03 = nullptr, evW = nullptr;
    if (s2 == nullptr) {
        cudaFuncSetAttribute(mma_gemm, cudaFuncAttributeMaxDynamicSharedMemorySize, SMB);
        cudaFuncSetAttribute(mma_gemm_fused, cudaFuncAttributeMaxDynamicSharedMemorySize, SMB);
        cudaStreamCreateWithFlags(&s2, cudaStreamNonBlocking);
        cudaStreamCreateWithFlags(&s3, cudaStreamNonBlocking);
        cudaEventCreateWithFlags(&evFork, cudaEventDisableTiming);
        cudaEventCreateWithFlags(&evH, cudaEventDisableTiming);
        cudaEventCreateWithFlags(&evAgg, cudaEventDisableTiming);
        cudaEventCreateWithFlags(&evW03, cudaEventDisableTiming);
        cudaEventCreateWithFlags(&evW, cudaEventDisableTiming);
    }

    // ---- fork: CSR setup on s2, weight pre-split on s3 ----
    cudaEventRecord(evFork, 0);
    cudaStreamWaitEvent(s2, evFork, 0);
    cudaStreamWaitEvent(s3, evFork, 0);

    padzero_kernel<<<NNODES, 64, 0, s2>>>();
    zero_deg_kernel<<<(NNODES + 255) / 256, 256, 0, s2>>>();
    count_deg_kernel<<<800, 256, 0, s2>>>(dst);
    scan1_kernel<<<49, 1024, 0, s2>>>();
    scan2_kernel<<<1, 1, 0, s2>>>();
    scan3_kernel<<<49, 1024, 0, s2>>>();
    fill_csr_kernel<<<800, 256, 0, s2>>>(src, dst);

    // slot 3l: fused [cw(256 rows) | aw(448 rows)] x Kpad=din; slot 3l+2: rw
    const int dinv[3] = {128, 256, 256};
    for (int l = 0; l < 3; l++) {
        int K = dinv[l];
        int n1 = 256 * K;
        wsplit_kernel<<<(n1 + 255) / 256, 256, 0, s3>>>(cw[l], K, 256, 256, K, 3 * l, 0);
        int n2 = 448 * K;
        wsplit_kernel<<<(n2 + 255) / 256, 256, 0, s3>>>(aw[l], K, 400, 448, K, 3 * l, 256);
        int dout = (l < 2) ? 256 : 128;
        int n3 = dout * 512;
        wsplit_kernel<<<(n3 + 255) / 256, 256, 0, s3>>>(rw[l], 456, dout, dout, 512, 3 * l + 2, 0);
        if (l == 0) cudaEventRecord(evW03, s3);
    }
    cudaEventRecord(evW, s3);

    // ---- main stream: input conversion; wait only for layer-0 weights ----
    xsplit_kernel<<<(NNODES * 128 + 255) / 256, 256>>>(x_in, (long)NNODES * 128);
    cudaStreamWaitEvent(0, evW03, 0);

    for (int l = 0; l < 3; l++) {
        if (l == 1) cudaStreamWaitEvent(0, evW, 0);
        int din = dinv[l];
        const __nv_bfloat16* sh = p_wh + (size_t)(3 * l) * WSLOT;
        const __nv_bfloat16* sl = p_wl + (size_t)(3 * l) * WSLOT;
        const __nv_bfloat16* rwh = p_wh + (size_t)(3 * l + 2) * WSLOT;
        const __nv_bfloat16* rwl = p_wl + (size_t)(3 * l + 2) * WSLOT;

        // fused: h = x@cw ; t = relu(x@aw + ab)  (11 column tiles)
        mma_gemm_fused<<<dim3(11, MB), 256, SMB>>>(
            p_xhi, p_xlo, sh, sl, ab[l], p_h, p_t, NNODES, din);
        cudaEventRecord(evH, 0);

        // side stream: aggregation (fills GEMM drain + low-rank region)
        cudaStreamWaitEvent(s2, evH, 0);
        agg_kernel<<<NNODES, HD, 0, s2>>>(cb[l]);
        cudaEventRecord(evAgg, s2);

        // main: low-rank path
        zero_misc_kernel<<<(KLR * KLR + 255) / 256, 256>>>();
        colsum_kernel<<<(NNODES + 255) / 256, 256>>>();
        nf_kernel<<<1, 32>>>();
        vtz_kernel<<<200, 256>>>();
        respack_kernel<<<NNODES / 16, 256>>>();

        // join: combine needs agg output
        cudaStreamWaitEvent(0, evAgg, 0);
        if (l < 2) {
            mma_gemm<<<dim3(HD / 64, MB), 256, SMB>>>(
                p_chi, p_clo, rwh, rwl, rb[l], p_x, NNODES, GDC, HD, HD, 1);
            bn_stats_kernel<<<(NNODES + 127) / 128, 256>>>();
            bn_final_kernel<<<1, HD>>>(gam[l], bet[l]);
            bn_apply_kernel<<<(NNODES * HD + 255) / 256, 256>>>();
        } else {
            mma_gemm<<<dim3(2, MB), 256, SMB>>>(
                p_chi, p_clo, rwh, rwl, rb[l], out, NNODES, GDC, 128, 128, 0);
        }
    }
}